// round 17
// baseline (speedup 1.0000x reference)
#include <cuda_runtime.h>
#include <cstdint>

#define B_     8
#define N_     2048
#define FIN    256
#define FOUT   64
#define LOG2E  1.4426950408889634f
#define ONE_H2 0x3c003c00u   // fp16x2 {1.0, 1.0}

// Scratch (device globals: allocation-free rule)
__device__ uint2  g_WhH[B_ * N_ * FOUT / 4];  // fp16 Wh, quad layout [b][j>>4][o][c]
__device__ uint2  g_Wq[4096];                 // fp16 W quads [kb][o][c] (32KB, L2-resident)
__device__ float  g_esrc[B_ * N_];            // log2-scaled src logits
__device__ float2 g_edEF[B_ * N_];            // per node: (exp2(d), exp2(0.2 d))

// ---------------------------------------------------------------------------
// helpers
// ---------------------------------------------------------------------------
__device__ __forceinline__ uint32_t smem_u32(const void* p) {
    uint32_t a;
    asm("{ .reg .u64 t; cvta.to.shared.u64 t, %1; cvt.u32.u64 %0, t; }" : "=r"(a) : "l"(p));
    return a;
}
__device__ __forceinline__ void cpa16(uint32_t dst, const void* src) {
    asm volatile("cp.async.cg.shared.global [%0], [%1], 16;" :: "r"(dst), "l"(src));
}
#define CP_COMMIT() asm volatile("cp.async.commit_group;" ::: "memory")
#define CP_WAIT1()  asm volatile("cp.async.wait_group 1;" ::: "memory")
#define CP_WAIT2()  asm volatile("cp.async.wait_group 2;" ::: "memory")
#define BAR_PAIR(id) asm volatile("bar.sync %0, 128;" :: "r"(id) : "memory")

__device__ __forceinline__ float ex2f(float x) {
    float r; asm("ex2.approx.f32 %0, %1;" : "=f"(r) : "f"(x)); return r;
}
__device__ __forceinline__ uint32_t f16x2(float hi, float lo) {
    uint32_t r;
    asm("cvt.rn.satfinite.f16x2.f32 %0, %1, %2;" : "=r"(r) : "f"(hi), "f"(lo));
    return r;
}
// D += A*B, m16n8k16 fp16 -> f32 accum (base PTX ISA)
#define MMA_F16(d, a0, a1, a2, a3, b0, b1)                                    \
    asm volatile("mma.sync.aligned.m16n8k16.row.col.f32.f16.f16.f32 "         \
                 "{%0,%1,%2,%3}, {%4,%5,%6,%7}, {%8,%9}, {%0,%1,%2,%3};"      \
                 : "+f"((d)[0]), "+f"((d)[1]), "+f"((d)[2]), "+f"((d)[3])     \
                 : "r"(a0), "r"(a1), "r"(a2), "r"(a3), "r"(b0), "r"(b1))

// ---------------------------------------------------------------------------
// Kernel WQ: build fp16 W quads ONCE (16 blocks x 256 thr, coalesced via
// smem transpose). Replaces 256x redundant scattered W reads in prep
// (was ~131MB of L2 sector traffic -> now 64KB read + 32KB write).
// ---------------------------------------------------------------------------
__global__ void gat_wq(const float* __restrict__ W) {
    __shared__ float ws[16 * 64];
    int t = threadIdx.x;
    int kb = blockIdx.x;
    ((float4*)ws)[t] = ((const float4*)(W + (size_t)kb * 1024))[t];
    __syncthreads();
    int o = t >> 2, c = t & 3;
    float w00 = ws[(2 * c) * 64 + o],     w01 = ws[(2 * c + 1) * 64 + o];
    float w10 = ws[(2 * c + 8) * 64 + o], w11 = ws[(2 * c + 9) * 64 + o];
    uint2 pk;
    pk.x = f16x2(w01, w00);
    pk.y = f16x2(w11, w10);
    g_Wq[(size_t)kb * 256 + t] = pk;
}

// ---------------------------------------------------------------------------
// Kernel PREP: Wh = h @ W via fp16 tensor-core MMA (f32 accum).
// 256 blocks x 256 threads, 64 rows/block, 2 blocks/SM (84KB smem).
// W quads cp.async'd from L2-resident g_Wq (32KB contiguous); h quads built
// from cp.async-pipelined fp32 chunks; 16-kb MMA burst; dump -> smem;
// e_src/e_dst dots + EF + coalesced fp16 quad stores.
// ---------------------------------------------------------------------------
#define WQ_OFF  0          // 4096 uint2 = 32KB
#define HQ_OFF  32768      // 4096 uint2 = 32KB
#define H32_OFF 65536      // 2 x 9216 fp32 chunk bufs; reused as sT (16.9KB)
#define SMEM_A  (65536 + 18432)   // 83968

__global__ __launch_bounds__(256, 2) void gat_prep(const float* __restrict__ h,
                                                   const float* __restrict__ a) {
    extern __shared__ char sA[];
    uint2* wq = (uint2*)(sA + WQ_OFF);
    uint2* hq = (uint2*)(sA + HQ_OFF);
    float* hb = (float*)(sA + H32_OFF);
    uint32_t smbase = smem_u32(sA);
    uint32_t hbase = smbase + H32_OFF;

    int t = threadIdx.x;
    int row0 = blockIdx.x * 64;

    int r0 = t >> 3, f0 = t & 7;
    int r1 = (t + 256) >> 3;
    const float* hsrc = h + (size_t)row0 * FIN;

    // group 0: h chunk 0 + ALL W quads (L2 hits)
    cpa16(hbase + r0 * 144 + f0 * 16, hsrc + (size_t)r0 * FIN + f0 * 4);
    cpa16(hbase + r1 * 144 + f0 * 16, hsrc + (size_t)r1 * FIN + f0 * 4);
#pragma unroll
    for (int i = 0; i < 8; i++)
        cpa16(smbase + WQ_OFF + (i * 256 + t) * 16,
              (const char*)g_Wq + (size_t)(i * 256 + t) * 16);
    CP_COMMIT();
    // group 1: h chunk 1
    cpa16(hbase + 9216 + r0 * 144 + f0 * 16, hsrc + (size_t)r0 * FIN + 32 + f0 * 4);
    cpa16(hbase + 9216 + r1 * 144 + f0 * 16, hsrc + (size_t)r1 * FIN + 32 + f0 * 4);
    CP_COMMIT();

    // h chunks -> h quads, double-buffered
    for (int c = 0; c < 8; c++) {
        CP_WAIT1();
        __syncthreads();
        const float* hc = hb + (c & 1) * 2304;
#pragma unroll
        for (int i = 0; i < 2; i++) {
            int idx = i * 256 + t;            // 512 quads: (kbl, row, c)
            int kbl = idx >> 8, r2 = idx & 255;
            int row = r2 >> 2, cq = r2 & 3;
            const float* hr = hc + row * 36 + kbl * 16;
            float v0 = hr[2 * cq],     v1 = hr[2 * cq + 1];
            float v2 = hr[2 * cq + 8], v3 = hr[2 * cq + 9];
            uint2 pk;
            pk.x = f16x2(v1, v0);
            pk.y = f16x2(v3, v2);
            hq[((2 * c + kbl) * 64 + row) * 4 + cq] = pk;
        }
        __syncthreads();
        if (c + 2 < 8) {
            uint32_t dst = hbase + (c & 1) * 9216;
            const float* src = hsrc + (c + 2) * 32;
            cpa16(dst + r0 * 144 + f0 * 16, src + (size_t)r0 * FIN + f0 * 4);
            cpa16(dst + r1 * 144 + f0 * 16, src + (size_t)r1 * FIN + f0 * 4);
        }
        CP_COMMIT();
    }
    __syncthreads();

    // MMA burst: warp (mi = w>>1 rows mi*16..+15(+8), nh = w&1 out-half)
    int w = t >> 5, lane = t & 31;
    int q = lane >> 2, cq = lane & 3;
    int mi = w >> 1, nh = w & 1;

    float acc[4][4];
#pragma unroll
    for (int nt = 0; nt < 4; nt++)
#pragma unroll
        for (int s = 0; s < 4; s++) acc[nt][s] = 0.f;

#pragma unroll 4
    for (int kb = 0; kb < 16; kb++) {
        uint2 a02 = hq[((kb * 64) + (mi * 16 + q)) * 4 + cq];
        uint2 a13 = hq[((kb * 64) + (mi * 16 + q + 8)) * 4 + cq];
#pragma unroll
        for (int nt = 0; nt < 4; nt++) {
            uint2 bb = wq[((kb * 64) + (nh * 32 + nt * 8 + q)) * 4 + cq];
            MMA_F16(acc[nt], a02.x, a13.x, a02.y, a13.y, bb.x, bb.y);
        }
    }
    __syncthreads();

    // dump accums -> sT[row][col] (64 x 66)
    float* sT = (float*)(sA + H32_OFF);
#pragma unroll
    for (int nt = 0; nt < 4; nt++) {
        int col = nh * 32 + nt * 8 + 2 * cq;
        int row = mi * 16 + q;
        *(float2*)(sT + row * 66 + col)       = make_float2(acc[nt][0], acc[nt][1]);
        *(float2*)(sT + (row + 8) * 66 + col) = make_float2(acc[nt][2], acc[nt][3]);
    }
    __syncthreads();

    // epilogue: dots (e_src/e_dst), EF, fp16 quad stores
    int rg = t >> 4, op = t & 15;
    int ov[4] = {2 * op, 2 * op + 1, 2 * op + 32, 2 * op + 33};
    float a1v[4], a2v[4];
#pragma unroll
    for (int s = 0; s < 4; s++) { a1v[s] = a[ov[s]]; a2v[s] = a[FOUT + ov[s]]; }

#pragma unroll
    for (int q2 = 0; q2 < 4; q2++) {
        int r = rg * 4 + q2;
        int grow = row0 + r;
        float v1 = 0.f, v2 = 0.f;
#pragma unroll
        for (int s = 0; s < 4; s++) {
            float v = sT[r * 66 + ov[s]];
            v1 += v * a1v[s];
            v2 += v * a2v[s];
        }
#pragma unroll
        for (int off = 1; off < 16; off <<= 1) {
            v1 += __shfl_xor_sync(0xffffffffu, v1, off);
            v2 += __shfl_xor_sync(0xffffffffu, v2, off);
        }
        if (op == 0) {
            float s = v1 * LOG2E, d = v2 * LOG2E;
            g_esrc[grow] = s;
            g_edEF[grow] = make_float2(ex2f(d), ex2f(0.2f * d));
        }
    }

    // fp16 quad stores: block region = 1024 uint2 contiguous, coalesced
    uint2* gdst = g_WhH + (size_t)blockIdx.x * 1024;
    int o = t >> 2, cs = t & 3;
#pragma unroll
    for (int k = 0; k < 4; k++) {
        int jl = k * 16 + 2 * cs;
        float v00 = sT[jl * 66 + o],       v01 = sT[(jl + 1) * 66 + o];
        float v10 = sT[(jl + 8) * 66 + o], v11 = sT[(jl + 9) * 66 + o];
        uint2 pk;
        pk.x = f16x2(v01, v00);
        pk.y = f16x2(v11, v10);
        gdst[k * 256 + t] = pk;
    }
}

// ---------------------------------------------------------------------------
// Kernel B: streaming attention, fp16 m16n8k16 P @ Wh (f32 accum).
// Grid (32,8), 256 thr, 2 blk/SM. 2 PAIRS of 4 warps; slice = fp16 Wh 4KB +
// raw adj 9KB + EF 256B. NOW 4-deep cp.async pipeline (3 chunks of lead,
// wait_group 2) for DRAM-latency tolerance; pre-scaled pointer arithmetic.
// adj touched once chip-wide. p = adj>0 ? 2^-2*max(Ei*Ej, Fi*Fj) : 0;
// rowsum via ones-B MMA (same fp16 p -> exact normalization).
// ---------------------------------------------------------------------------
#define ADJ_OFF  4096
#define EF_OFF   13312
#define SLICE_SZ 13568                     // 4096 Wh + 9216 adj + 256 EF
#define SM_TOTB  (2 * 4 * SLICE_SZ)        // 108544

__device__ __forceinline__ void pf_slice(uint32_t dst, const char* wsrc,
                                         const char* asrc, const char* esrc,
                                         int lt) {
    // Wh fp16 quads: 4KB contiguous
#pragma unroll
    for (int i = 0; i < 2; i++)
        cpa16(dst + (lt + 128 * i) * 16, wsrc + (size_t)(lt + 128 * i) * 16);
    // adj: 64 rows x 128B, row stride 8KB in gmem, 144B in smem
#pragma unroll
    for (int i = 0; i < 4; i++) {
        int idx = i * 128 + lt;
        int r = idx >> 3, u = idx & 7;
        cpa16(dst + ADJ_OFF + r * 144 + u * 16, asrc + ((size_t)r << 13) + u * 16);
    }
    if (lt < 16)
        cpa16(dst + EF_OFF + lt * 16, esrc + lt * 16);
}

__global__ __launch_bounds__(256, 2) void gat_attn(const int* __restrict__ adj,
                                                   float* __restrict__ out) {
    extern __shared__ char sm[];
    uint32_t smb = smem_u32(sm);

    int t = threadIdx.x;
    int w = t >> 5, lane = t & 31;
    int q = lane >> 2, c = lane & 3;
    int b = blockIdx.y;
    int i0 = blockIdx.x * 64;
    int rowbase = b * N_;
    int jq = w >> 2, wp = w & 3;
    int lr0 = wp * 16 + q;
    int lt = t & 127;
    uint32_t slice0 = smb + jq * 4 * SLICE_SZ;

    // pre-scaled stream pointers (chunk stride: Wh 4KB, adj 128B, EF 256B)
    const char* wsrc0 = (const char*)g_WhH + (size_t)b * (N_ * FOUT * 2)
                        + (size_t)jq * 131072;
    const char* asrc0 = (const char*)(adj + ((size_t)(rowbase + i0) << 11))
                        + (size_t)jq * 4096;
    const char* esrc0 = (const char*)(g_edEF + rowbase) + (size_t)jq * 8192;

    float si0 = g_esrc[rowbase + i0 + lr0];
    float si8 = g_esrc[rowbase + i0 + lr0 + 8];
    float Ei0 = ex2f(si0 - 2.0f), Fi0 = ex2f(0.2f * si0 - 2.0f);
    float Ei8 = ex2f(si8 - 2.0f), Fi8 = ex2f(0.2f * si8 - 2.0f);

    // prologue: 3 chunks in flight
#pragma unroll
    for (int pc = 0; pc < 3; pc++) {
        pf_slice(slice0 + pc * SLICE_SZ, wsrc0 + pc * 4096,
                 asrc0 + pc * 128, esrc0 + pc * 256, lt);
        CP_COMMIT();
    }

    float acc[8][4];
#pragma unroll
    for (int nt = 0; nt < 8; nt++)
#pragma unroll
        for (int s = 0; s < 4; s++) acc[nt][s] = 0.f;
    float acc_rs[4] = {0.f, 0.f, 0.f, 0.f};

#pragma unroll 1
    for (int cc = 0; cc < 32; cc++) {
        CP_WAIT2();
        BAR_PAIR(jq + 1);
        if (cc + 3 < 32)
            pf_slice(slice0 + ((cc + 3) & 3) * SLICE_SZ, wsrc0 + (cc + 3) * 4096,
                     asrc0 + (size_t)(cc + 3) * 128, esrc0 + (cc + 3) * 256, lt);
        CP_COMMIT();

        const char*  Sc = sm + (size_t)(jq * 4 + (cc & 3)) * SLICE_SZ;
        const int*   Ac = (const int*)(Sc + ADJ_OFF);
        const float* Ec = (const float*)(Sc + EF_OFF);

#pragma unroll
        for (int kb = 0; kb < 2; kb++) {
            int base0 = lr0 * 36 + kb * 16 + 2 * c;
            int2 x0 = *(const int2*)(Ac + base0);
            int2 x1 = *(const int2*)(Ac + base0 + 8);
            int2 y0 = *(const int2*)(Ac + base0 + 288);
            int2 y1 = *(const int2*)(Ac + base0 + 296);
            float4 ef0 = *(const float4*)(Ec + (kb * 16 + 2 * c) * 2);
            float4 ef1 = *(const float4*)(Ec + (kb * 16 + 2 * c + 8) * 2);

            float p00 = x0.x > 0 ? fmaxf(Ei0 * ef0.x, Fi0 * ef0.y) : 0.f;
            float p01 = x0.y > 0 ? fmaxf(Ei0 * ef0.z, Fi0 * ef0.w) : 0.f;
            float p80 = y0.x > 0 ? fmaxf(Ei8 * ef0.x, Fi8 * ef0.y) : 0.f;
            float p81 = y0.y > 0 ? fmaxf(Ei8 * ef0.z, Fi8 * ef0.w) : 0.f;
            float p08 = x1.x > 0 ? fmaxf(Ei0 * ef1.x, Fi0 * ef1.y) : 0.f;
            float p09 = x1.y > 0 ? fmaxf(Ei0 * ef1.z, Fi0 * ef1.w) : 0.f;
            float p88 = y1.x > 0 ? fmaxf(Ei8 * ef1.x, Fi8 * ef1.y) : 0.f;
            float p89 = y1.y > 0 ? fmaxf(Ei8 * ef1.z, Fi8 * ef1.w) : 0.f;

            uint32_t a0 = f16x2(p01, p00);
            uint32_t a1 = f16x2(p81, p80);
            uint32_t a2 = f16x2(p09, p08);
            uint32_t a3 = f16x2(p89, p88);

            const uint2* bq = (const uint2*)(Sc + kb * 2048);
#pragma unroll
            for (int nt = 0; nt < 8; nt++) {
                uint2 bb = bq[(nt * 8 + q) * 4 + c];
                MMA_F16(acc[nt], a0, a1, a2, a3, bb.x, bb.y);
            }
            MMA_F16(acc_rs, a0, a1, a2, a3, ONE_H2, ONE_H2);
        }
    }

    // combine the 2 j-halves via smem (reuses staging)
    float* dsm = (float*)sm;                 // [64][66]
    float* rsm = (float*)(sm + 16896);       // [64]
    __syncthreads();
    if (jq == 1) {
#pragma unroll
        for (int nt = 0; nt < 8; nt++) {
            *(float2*)(dsm + lr0 * 66 + nt * 8 + 2 * c) =
                make_float2(acc[nt][0], acc[nt][1]);
            *(float2*)(dsm + (lr0 + 8) * 66 + nt * 8 + 2 * c) =
                make_float2(acc[nt][2], acc[nt][3]);
        }
        if (c == 0) {
            rsm[lr0]     = acc_rs[0];
            rsm[lr0 + 8] = acc_rs[2];
        }
    }
    __syncthreads();
    if (jq == 0) {
        float i0v = 1.0f / (acc_rs[0] + rsm[lr0]);
        float i8v = 1.0f / (acc_rs[2] + rsm[lr0 + 8]);
        float* o0 = out + (size_t)(rowbase + i0 + lr0) * FOUT;
        float* o8 = out + (size_t)(rowbase + i0 + lr0 + 8) * FOUT;
#pragma unroll
        for (int nt = 0; nt < 8; nt++) {
            int col = nt * 8 + 2 * c;
            float2 d0 = *(const float2*)(dsm + lr0 * 66 + col);
            float2 d8 = *(const float2*)(dsm + (lr0 + 8) * 66 + col);
            float y;
            float2 v0, v8;
            y = (acc[nt][0] + d0.x) * i0v; v0.x = y > 0.f ? y : expm1f(y);
            y = (acc[nt][1] + d0.y) * i0v; v0.y = y > 0.f ? y : expm1f(y);
            y = (acc[nt][2] + d8.x) * i8v; v8.x = y > 0.f ? y : expm1f(y);
            y = (acc[nt][3] + d8.y) * i8v; v8.y = y > 0.f ? y : expm1f(y);
            *(float2*)(o0 + col) = v0;
            *(float2*)(o8 + col) = v8;
        }
    }
}

// ---------------------------------------------------------------------------
extern "C" void kernel_launch(void* const* d_in, const int* in_sizes, int n_in,
                              void* d_out, int out_size) {
    const float* h   = (const float*)d_in[0];
    const int*   adj = (const int*)d_in[1];
    const float* W   = (const float*)d_in[2];
    const float* a   = (const float*)d_in[3];
    float*       out = (float*)d_out;

    cudaFuncSetAttribute(gat_prep, cudaFuncAttributeMaxDynamicSharedMemorySize, SMEM_A);
    cudaFuncSetAttribute(gat_attn, cudaFuncAttributeMaxDynamicSharedMemorySize, SM_TOTB);

    gat_wq<<<16, 256>>>(W);                       // W quads once (L2-resident)
    gat_prep<<<(B_ * N_) / 64, 256, SMEM_A>>>(h, a);

    dim3 gridB(N_ / 64, B_);   // (32, 8) = 256 blocks
    gat_attn<<<gridB, 256, SM_TOTB>>>(adj, out);
}